// round 16
// baseline (speedup 1.0000x reference)
#include <cuda_runtime.h>
#include <cuda_bf16.h>
#include <math.h>

#define BB 8
#define NPT 2048
#define PT (BB*NPT)

// ---------------- scratch (device globals; no runtime allocation) ----------------
__device__ float g_simi[(size_t)BB*NPT*NPT];
__device__ float g_y3t [(size_t)PT*128];
__device__ unsigned g_xn_h[(size_t)PT*64],  g_xn_l[(size_t)PT*64];
__device__ unsigned g_yn_h[(size_t)PT*64],  g_yn_l[(size_t)PT*64];
__device__ unsigned g_xc_h[(size_t)PT*128], g_xc_l[(size_t)PT*128];
__device__ unsigned g_xf_h[(size_t)PT*256], g_xf_l[(size_t)PT*256];
__device__ float    g_h5 [(size_t)PT*512];
__device__ unsigned g_h5_h[(size_t)PT*256], g_h5_l[(size_t)PT*256];
__device__ float    g_h6 [(size_t)PT*512];
__device__ unsigned g_h6_h[(size_t)PT*256], g_h6_l[(size_t)PT*256];
__device__ float    g_h7 [(size_t)PT*256];
__device__ unsigned g_h7_h[(size_t)PT*128], g_h7_l[(size_t)PT*128];
__device__ float    g_embp[(size_t)PT*128];
__device__ unsigned g_w4_h[256*128],  g_w4_l[256*128];
__device__ unsigned g_w5_h[512*256],  g_w5_l[512*256];
__device__ unsigned g_m1_h[512*256],  g_m1_l[512*256];
__device__ unsigned g_m2_h[256*256],  g_m2_l[256*256];
__device__ unsigned g_m3_h[128*128],  g_m3_l[128*128];
__device__ float g_gsA[4*512];           // per-layer GN accumulators (sum, sumsq)
__device__ float g_gsum[BB*512];
__device__ unsigned g_gmax[BB*512];

// ---------------- helpers ----------------------------------------------------------
__device__ __forceinline__ void split2(float a, float b, unsigned& hi, unsigned& lo) {
    __nv_bfloat162 h = __floats2bfloat162_rn(a, b);
    float ra = a - __bfloat162float(h.x);
    float rb = b - __bfloat162float(h.y);
    __nv_bfloat162 l = __floats2bfloat162_rn(ra, rb);
    hi = *reinterpret_cast<unsigned*>(&h);
    lo = *reinterpret_cast<unsigned*>(&l);
}
__device__ __forceinline__ float hl_lo(unsigned h, unsigned l) {
    return __uint_as_float(h << 16) + __uint_as_float(l << 16);
}
__device__ __forceinline__ float hl_hi(unsigned h, unsigned l) {
    return __uint_as_float(h & 0xffff0000u) + __uint_as_float(l & 0xffff0000u);
}

#define MMA_BF16(ACC, AF, BF) \
    asm volatile( \
        "mma.sync.aligned.m16n8k16.row.col.f32.bf16.bf16.f32 " \
        "{%0,%1,%2,%3}, {%4,%5,%6,%7}, {%8,%9}, {%0,%1,%2,%3};" \
        : "+f"(ACC[0]), "+f"(ACC[1]), "+f"(ACC[2]), "+f"(ACC[3]) \
        : "r"(AF[0]), "r"(AF[1]), "r"(AF[2]), "r"(AF[3]), \
          "r"(BF[0]), "r"(BF[1]))

#define CPA16(DSTU, SRC) \
    asm volatile("cp.async.cg.shared.global [%0], [%1], 16;" :: "r"(DSTU), "l"(SRC))

#define LDSM_X4(R, ADR) \
    asm volatile("ldmatrix.sync.aligned.m8n8.x4.shared.b16 {%0,%1,%2,%3}, [%4];" \
        : "=r"((R)[0]), "=r"((R)[1]), "=r"((R)[2]), "=r"((R)[3]) : "r"(ADR))

// ---------------- init --------------------------------------------------------------
__global__ void zero_init_kernel() {
    int i = blockIdx.x*blockDim.x + threadIdx.x;
    if (i < BB*512) { g_gsum[i] = 0.f; g_gmax[i] = 0u; }
    if (i < 4*512)  g_gsA[i] = 0.f;
}

// ---------------- all weight splits, one launch -------------------------------------
__global__ void wsplit_all(const float* __restrict__ w4, const float* __restrict__ w5,
                           const float* __restrict__ m1, const float* __restrict__ m2,
                           const float* __restrict__ m3) {
    int t = blockIdx.x*256 + threadIdx.x;
    const float* src; unsigned *dh, *dl; int li;
    if      (t < 32768)  { src = w4; dh = g_w4_h; dl = g_w4_l; li = t; }
    else if (t < 163840) { src = w5; dh = g_w5_h; dl = g_w5_l; li = t - 32768; }
    else if (t < 294912) { src = m1; dh = g_m1_h; dl = g_m1_l; li = t - 163840; }
    else if (t < 360448) { src = m2; dh = g_m2_h; dl = g_m2_l; li = t - 294912; }
    else if (t < 376832) { src = m3; dh = g_m3_h; dl = g_m3_l; li = t - 360448; }
    else return;
    float2 v = ((const float2*)src)[li];
    unsigned h, l; split2(v.x, v.y, h, l);
    dh[li] = h; dl[li] = l;
}

// ---------------- [B,C,N] -> point-major hi/lo ---------------------------------------
__global__ void transpose_hl(const float* __restrict__ src, unsigned* __restrict__ dh,
                             unsigned* __restrict__ dl, int C, int dstLdU, int dstOffU) {
    __shared__ float tile[32][33];
    int b  = blockIdx.z;
    int n0 = blockIdx.x*32, c0 = blockIdx.y*32;
    const float* s = src + (size_t)b*C*NPT;
    for (int i = threadIdx.y; i < 32; i += 8)
        tile[i][threadIdx.x] = s[(size_t)(c0+i)*NPT + n0 + threadIdx.x];
    __syncthreads();
    int tid = threadIdx.y*32 + threadIdx.x;
    #pragma unroll
    for (int it = 0; it < 2; it++) {
        int pl = (tid >> 4) + it*16, up = tid & 15;
        unsigned h, l;
        split2(tile[up*2][pl], tile[up*2+1][pl], h, l);
        size_t idx = (size_t)(b*NPT + n0 + pl)*dstLdU + dstOffU + (c0 >> 1) + up;
        dh[idx] = h; dl[idx] = l;
    }
}

// ---------------- [B,C,N] -> point-major fp32 ---------------------------------------
__global__ void transpose_f(const float* __restrict__ src, float* __restrict__ dst, int C) {
    __shared__ float tile[32][33];
    int b  = blockIdx.z;
    int n0 = blockIdx.x*32, c0 = blockIdx.y*32;
    const float* s = src + (size_t)b*C*NPT;
    for (int i = threadIdx.y; i < 32; i += 8)
        tile[i][threadIdx.x] = s[(size_t)(c0+i)*NPT + n0 + threadIdx.x];
    __syncthreads();
    float* d = dst + (size_t)b*NPT*C;
    for (int i = threadIdx.y; i < 32; i += 8)
        d[(size_t)(n0+i)*C + c0 + threadIdx.x] = tile[threadIdx.x][i];
}

// ---------------- L2 normalize: x (hi/lo source) and y (fp32 source) merged ---------
__global__ void norm_xy(unsigned* __restrict__ xnh, unsigned* __restrict__ xnl,
                        unsigned* __restrict__ ynh, unsigned* __restrict__ ynl) {
    int p = blockIdx.x*4 + threadIdx.y;
    int t = threadIdx.x;
    float v0, v1;
    if (blockIdx.y == 0) {
        unsigned h = g_xf_h[(size_t)p*256 + 64 + t], l = g_xf_l[(size_t)p*256 + 64 + t];
        v0 = hl_lo(h, l); v1 = hl_hi(h, l);
    } else {
        float2 v = ((const float2*)g_y3t)[(size_t)p*64 + t];
        v0 = v.x; v1 = v.y;
    }
    float s = v0*v0 + v1*v1;
    #pragma unroll
    for (int o = 16; o; o >>= 1) s += __shfl_xor_sync(0xffffffffu, s, o);
    __shared__ float ws[8];
    int wid = threadIdx.y*2 + (t >> 5);
    if ((t & 31) == 0) ws[wid] = s;
    __syncthreads();
    float rs = rsqrtf(ws[threadIdx.y*2] + ws[threadIdx.y*2+1]);
    unsigned oh, ol; split2(v0*rs, v1*rs, oh, ol);
    if (blockIdx.y == 0) { xnh[(size_t)p*64 + t] = oh; xnl[(size_t)p*64 + t] = ol; }
    else                 { ynh[(size_t)p*64 + t] = oh; ynl[(size_t)p*64 + t] = ol; }
}

// ---------------- bf16x3 GEMM, cp.async pipeline + ldmatrix fragments --------------
// EPI 0: fp32 out   EPI 1: BN+LeakyReLU -> hi/lo   EPI 3: (+bias) fp32 + group stats
template<int EPI>
__global__ void __launch_bounds__(256, 2) gemm_hl(
    const unsigned* __restrict__ Ah, const unsigned* __restrict__ Al,
    const unsigned* __restrict__ Bh, const unsigned* __restrict__ Bl,
    float* __restrict__ C, unsigned* __restrict__ Ch, unsigned* __restrict__ Cl,
    int K, int ldc, int coffU,
    size_t sAU, size_t sBU, size_t sC,
    const float* __restrict__ p1, const float* __restrict__ p2,
    float* __restrict__ gsb, int chgShift)
{
    extern __shared__ __align__(16) unsigned sm[];
    __shared__ float sgs[64];
    const int KU = K >> 1;
    Ah += sAU*blockIdx.z; Al += sAU*blockIdx.z;
    Bh += sBU*blockIdx.z; Bl += sBU*blockIdx.z;
    C  += sC*blockIdx.z;
    const int row0 = blockIdx.y*128, col0 = blockIdx.x*128;
    const int tid  = threadIdx.x;
    const int lane = tid & 31, warp = tid >> 5;
    const int warpM = warp & 1, warpN = warp >> 1;

    if (EPI == 3 && tid < 64) sgs[tid] = 0.f;

    unsigned sbase = (unsigned)__cvta_generic_to_shared(sm);
    const int r0 = tid >> 2, q0 = (tid & 3) << 2;
    const unsigned aoff = (unsigned)((lane & 15)*80 + (lane >> 4)*16);
    const unsigned boff = (unsigned)(((lane & 7) + ((lane >> 4) << 3))*80
                                     + ((lane >> 3) & 1)*16);

    float acc[4][4][4];
    #pragma unroll
    for (int mi = 0; mi < 4; mi++)
        #pragma unroll
        for (int ni = 0; ni < 4; ni++)
            #pragma unroll
            for (int q = 0; q < 4; q++) acc[mi][ni][q] = 0.f;

    const int nk = K >> 5;

    auto issue = [&](int t, int stage) {
        int ku0 = (t << 4) + q0;
        unsigned dbase = sbase + (stage*10240 + r0*20 + q0)*4u;
        #pragma unroll
        for (int i = 0; i < 2; i++) {
            int r = r0 + i*64;
            unsigned d = dbase + i*(64*20*4u);
            CPA16(d,            Ah + (size_t)(row0+r)*KU + ku0);
            CPA16(d + 2560*4u,  Al + (size_t)(row0+r)*KU + ku0);
            CPA16(d + 5120*4u,  Bh + (size_t)(col0+r)*KU + ku0);
            CPA16(d + 7680*4u,  Bl + (size_t)(col0+r)*KU + ku0);
        }
        asm volatile("cp.async.commit_group;");
    };

    issue(0, 0);

    for (int t = 0; t < nk; t++) {
        int stage = t & 1;
        if (t + 1 < nk) {
            issue(t + 1, stage ^ 1);
            asm volatile("cp.async.wait_group 1;");
        } else {
            asm volatile("cp.async.wait_group 0;");
        }
        __syncthreads();
        unsigned stg = sbase + (unsigned)stage*40960u;
        #pragma unroll
        for (int kk = 0; kk < 2; kk++) {
            unsigned ah[4][4], al[4][4], bh[4][2], bl[4][2];
            #pragma unroll
            for (int mi = 0; mi < 4; mi++) {
                unsigned adr = stg + (unsigned)(((warpM*64 + mi*16)*20 + kk*8)*4) + aoff;
                LDSM_X4(ah[mi], adr);
                LDSM_X4(al[mi], adr + 10240u);
            }
            #pragma unroll
            for (int ni2 = 0; ni2 < 2; ni2++) {
                unsigned adr = stg + 20480u
                             + (unsigned)(((warpN*32 + ni2*16)*20 + kk*8)*4) + boff;
                unsigned rb[4];
                LDSM_X4(rb, adr);
                bh[ni2*2][0] = rb[0]; bh[ni2*2][1] = rb[1];
                bh[ni2*2+1][0] = rb[2]; bh[ni2*2+1][1] = rb[3];
                LDSM_X4(rb, adr + 10240u);
                bl[ni2*2][0] = rb[0]; bl[ni2*2][1] = rb[1];
                bl[ni2*2+1][0] = rb[2]; bl[ni2*2+1][1] = rb[3];
            }
            #pragma unroll
            for (int mi = 0; mi < 4; mi++)
                #pragma unroll
                for (int ni = 0; ni < 4; ni++) {
                    MMA_BF16(acc[mi][ni], ah[mi], bh[ni]);
                    MMA_BF16(acc[mi][ni], ah[mi], bl[ni]);
                    MMA_BF16(acc[mi][ni], al[mi], bh[ni]);
                }
        }
        __syncthreads();
    }

    float ls1[4] = {0.f,0.f,0.f,0.f}, ls2[4] = {0.f,0.f,0.f,0.f};

    #pragma unroll
    for (int mi = 0; mi < 4; mi++) {
        int r = row0 + warpM*64 + mi*16 + (lane >> 2);
        #pragma unroll
        for (int ni = 0; ni < 4; ni++) {
            int cc = col0 + warpN*32 + ni*8 + (lane & 3)*2;
            #pragma unroll
            for (int half = 0; half < 2; half++) {
                int rr = r + half*8;
                float v0 = acc[mi][ni][half*2 + 0];
                float v1 = acc[mi][ni][half*2 + 1];
                if (EPI == 1) {
                    v0 = v0 * (p1[cc]   * 0.9999950000374998f) + p2[cc];
                    v1 = v1 * (p1[cc+1] * 0.9999950000374998f) + p2[cc+1];
                    v0 = v0 >= 0.f ? v0 : 0.2f*v0;
                    v1 = v1 >= 0.f ? v1 : 0.2f*v1;
                    unsigned oh, ol; split2(v0, v1, oh, ol);
                    size_t idx = (size_t)rr*(ldc>>1) + coffU + (cc >> 1);
                    Ch[idx] = oh; Cl[idx] = ol;
                } else {
                    if (EPI == 3 && p2) { v0 += p2[cc]; v1 += p2[cc+1]; }
                    *(float2*)(C + (size_t)rr*ldc + cc) = make_float2(v0, v1);
                    if (EPI == 3) {
                        ls1[ni] += v0 + v1;
                        ls2[ni] += v0*v0 + v1*v1;
                    }
                }
            }
        }
    }

    if (EPI == 3) {
        int b = row0 >> 11;
        if (chgShift >= 3) {
            #pragma unroll
            for (int ni = 0; ni < 4; ni++) {
                float v1s = ls1[ni], v2s = ls2[ni];
                #pragma unroll
                for (int o = 16; o; o >>= 1) {
                    v1s += __shfl_xor_sync(0xffffffffu, v1s, o);
                    v2s += __shfl_xor_sync(0xffffffffu, v2s, o);
                }
                if (lane == 0) {
                    int gl = (warpN*32 + ni*8) >> chgShift;
                    atomicAdd(&sgs[gl*2],   v1s);
                    atomicAdd(&sgs[gl*2+1], v2s);
                }
            }
        } else {
            #pragma unroll
            for (int ni = 0; ni < 4; ni++) {
                int gl = (warpN*32 + ni*8 + (lane & 3)*2) >> chgShift;
                atomicAdd(&sgs[gl*2],   ls1[ni]);
                atomicAdd(&sgs[gl*2+1], ls2[ni]);
            }
        }
        __syncthreads();
        int ng = 128 >> chgShift;
        if (tid < ng) {
            int g = (col0 >> chgShift) + tid;
            atomicAdd(&gsb[(b*32 + g)*2],   sgs[tid*2]);
            atomicAdd(&gsb[(b*32 + g)*2+1], sgs[tid*2+1]);
        }
    }
}

// ---------------- top-20 + softmax + neighbor aggregation (register-resident) -------
__global__ void __launch_bounds__(256) topk_agg() {
    __shared__ float tv[20]; __shared__ int tix[20];
    __shared__ float wgt[20];
    __shared__ float wmax[8]; __shared__ int wmi[8];
    __shared__ int sbi;
    int p = blockIdx.x;
    int b = p >> 11;
    const float* s = g_simi + (size_t)p*2048;
    int tid = threadIdx.x;

    // each thread owns elements tid + j*256 in registers
    float v[8];
    #pragma unroll
    for (int j = 0; j < 8; j++) v[j] = s[tid + j*256];

    for (int it = 0; it < 20; it++) {
        // local max (ascending j => lowest index wins ties via strict >)
        float m = v[0]; int mj = 0;
        #pragma unroll
        for (int j = 1; j < 8; j++)
            if (v[j] > m) { m = v[j]; mj = j; }
        int mi = tid + mj*256;
        #pragma unroll
        for (int o = 16; o; o >>= 1) {
            float ov = __shfl_xor_sync(0xffffffffu, m, o);
            int   oi = __shfl_xor_sync(0xffffffffu, mi, o);
            if (ov > m || (ov == m && oi < mi)) { m = ov; mi = oi; }
        }
        if ((tid & 31) == 0) { wmax[tid>>5] = m; wmi[tid>>5] = mi; }
        __syncthreads();
        if (tid == 0) {
            float bm = wmax[0]; int bi = wmi[0];
            for (int w = 1; w < 8; w++)
                if (wmax[w] > bm || (wmax[w] == bm && wmi[w] < bi)) { bm = wmax[w]; bi = wmi[w]; }
            tv[it] = bm; tix[it] = bi; sbi = bi;
        }
        __syncthreads();
        int bi = sbi;
        if ((bi & 255) == tid) v[bi >> 8] = -INFINITY;   // invalidate winner
        __syncthreads();
    }

    if (tid == 0) {
        float mx = tv[0], sum = 0.f;
        float e[20];
        #pragma unroll
        for (int k = 0; k < 20; k++) { e[k] = expf(tv[k]-mx); sum += e[k]; }
        float inv = 1.f/sum;
        #pragma unroll
        for (int k = 0; k < 20; k++) wgt[k] = e[k]*inv;
    }
    __syncthreads();

    if (tid < 64) {
        g_xc_h[(size_t)p*128 + tid] = g_xf_h[(size_t)p*256 + 64 + tid];
        g_xc_l[(size_t)p*128 + tid] = g_xf_l[(size_t)p*256 + 64 + tid];
    } else if (tid < 128) {
        int t2 = tid - 64;
        const float2* yb = (const float2*)(g_y3t + (size_t)b*NPT*128);
        float a0 = 0.f, a1 = 0.f;
        #pragma unroll
        for (int k = 0; k < 20; k++) {
            float2 yv = yb[(size_t)tix[k]*64 + t2];
            a0 += wgt[k]*yv.x; a1 += wgt[k]*yv.y;
        }
        unsigned h = g_xf_h[(size_t)p*256 + 64 + t2], l = g_xf_l[(size_t)p*256 + 64 + t2];
        unsigned oh, ol;
        split2(a0 - hl_lo(h, l), a1 - hl_hi(h, l), oh, ol);
        g_xc_h[(size_t)p*128 + 64 + t2] = oh;
        g_xc_l[(size_t)p*128 + 64 + t2] = ol;
    }
}

// ---------------- GN apply + ReLU -> hi/lo (inline stats, 4 elems/thread) ----------
__global__ void gn_apply_hl(const float* __restrict__ x, unsigned* __restrict__ oh,
                            unsigned* __restrict__ ol, const float* __restrict__ gam,
                            const float* __restrict__ bet, const float* __restrict__ gs,
                            float rcnt, int Cshift, int chgShift) {
    size_t q = (size_t)blockIdx.x*256 + threadIdx.x;   // quad index
    size_t e0 = q*4;
    int c0 = (int)(e0 & ((1u<<Cshift)-1u));
    int b  = (int)(e0 >> Cshift) >> 11;
    int grp = c0 >> chgShift;       // quad never crosses a group (chgShift >= 3)
    float s1 = gs[(b*32+grp)*2], s2 = gs[(b*32+grp)*2+1];
    float mu = s1*rcnt;
    float rs = rsqrtf(s2*rcnt - mu*mu + 1e-5f);
    float4 xv = ((const float4*)x)[q];
    float v0 = fmaxf((xv.x-mu)*rs*gam[c0]   + bet[c0],   0.f);
    float v1 = fmaxf((xv.y-mu)*rs*gam[c0+1] + bet[c0+1], 0.f);
    float v2 = fmaxf((xv.z-mu)*rs*gam[c0+2] + bet[c0+2], 0.f);
    float v3 = fmaxf((xv.w-mu)*rs*gam[c0+3] + bet[c0+3], 0.f);
    unsigned h0, l0, h1, l1;
    split2(v0, v1, h0, l0);
    split2(v2, v3, h1, l1);
    oh[q*2] = h0; oh[q*2+1] = h1;
    ol[q*2] = l0; ol[q*2+1] = l1;
}

// ---------------- conv5 GN apply + LeakyReLU + gmax/gavg -> hi/lo (inline stats) ----
__global__ void gn_apply5_hl(const float* __restrict__ x, unsigned* __restrict__ oh,
                             unsigned* __restrict__ ol, const float* __restrict__ gam,
                             const float* __restrict__ bet, const float* __restrict__ gs) {
    int b = blockIdx.y;
    int p0 = blockIdx.x*128;
    int t = threadIdx.x;
    int c0 = t*2;
    int grp = c0 >> 4;
    float s1v = gs[(b*32+grp)*2], s2v = gs[(b*32+grp)*2+1];
    float mu = s1v*(1.f/32768.f);
    float rs = rsqrtf(s2v*(1.f/32768.f) - mu*mu + 1e-5f);
    float ga0 = rs*gam[c0],   bb0 = bet[c0]   - mu*ga0;
    float ga1 = rs*gam[c0+1], bb1 = bet[c0+1] - mu*ga1;
    float s0 = 0.f, s1 = 0.f, m0 = -INFINITY, m1 = -INFINITY;
    size_t base = ((size_t)b*NPT + p0)*256 + t;
    for (int p = 0; p < 128; p++) {
        size_t idx = base + (size_t)p*256;
        float2 xv = ((const float2*)x)[idx];
        float v0 = xv.x*ga0 + bb0; v0 = v0 >= 0.f ? v0 : 0.2f*v0;
        float v1 = xv.y*ga1 + bb1; v1 = v1 >= 0.f ? v1 : 0.2f*v1;
        unsigned h, l; split2(v0, v1, h, l);
        oh[idx] = h; ol[idx] = l;
        s0 += v0; s1 += v1; m0 = fmaxf(m0, v0); m1 = fmaxf(m1, v1);
    }
    atomicAdd(&g_gsum[b*512+c0],   s0);
    atomicAdd(&g_gsum[b*512+c0+1], s1);
    unsigned u0 = __float_as_uint(m0);
    u0 = (u0 & 0x80000000u) ? ~u0 : (u0 | 0x80000000u);
    atomicMax(&g_gmax[b*512+c0], u0);
    unsigned u1 = __float_as_uint(m1);
    u1 = (u1 & 0x80000000u) ? ~u1 : (u1 | 0x80000000u);
    atomicMax(&g_gmax[b*512+c0+1], u1);
}

// ---------------- FUSED: emb GN apply + ReLU + transpose (inline stats) -------------
__global__ void gn_emb_out(const float* __restrict__ e, float* __restrict__ dst,
                           const float* __restrict__ gam, const float* __restrict__ bet,
                           const float* __restrict__ gs) {
    __shared__ float tile[32][33];
    int b = blockIdx.z;
    int n0 = blockIdx.x*32, c0 = blockIdx.y*32;
    int c = c0 + threadIdx.x;
    int grp = c >> 2;
    float s1 = gs[(b*32+grp)*2], s2 = gs[(b*32+grp)*2+1];
    float mu = s1*(1.f/8192.f);
    float rs = rsqrtf(s2*(1.f/8192.f) - mu*mu + 1e-5f);
    float ga = rs*gam[c], bb = bet[c] - mu*ga;
    const float* s = e + (size_t)b*NPT*128;
    for (int i = threadIdx.y; i < 32; i += 8) {
        float v = s[(size_t)(n0+i)*128 + c];
        tile[i][threadIdx.x] = fmaxf(v*ga + bb, 0.f);
    }
    __syncthreads();
    float* d = dst + (size_t)b*128*NPT;
    for (int i = threadIdx.y; i < 32; i += 8)
        d[(size_t)(c0+i)*NPT + n0 + threadIdx.x] = tile[threadIdx.x][i];
}

// ---------------- output: global vector [B,1024] -----------------------------------
__global__ void gv_out(float* __restrict__ dst) {
    int i = blockIdx.x*blockDim.x + threadIdx.x;
    int b = i >> 10, c = i & 1023;
    float v;
    if (c < 512) {
        unsigned u = g_gmax[b*512+c];
        unsigned f = (u & 0x80000000u) ? (u ^ 0x80000000u) : ~u;
        v = __uint_as_float(f);
    } else {
        v = g_gsum[b*512 + c - 512] * (1.f/2048.f);
    }
    dst[i] = v;
}

// ===================================================================================
extern "C" void kernel_launch(void* const* d_in, const int* in_sizes, int n_in,
                              void* d_out, int out_size) {
    const float* x1   = (const float*)d_in[0];
    const float* x2   = (const float*)d_in[1];
    const float* x3   = (const float*)d_in[2];
    const float* y3   = (const float*)d_in[3];
    const float* w4   = (const float*)d_in[4];
    const float* bn4g = (const float*)d_in[5];
    const float* bn4b = (const float*)d_in[6];
    const float* w5   = (const float*)d_in[7];
    const float* gn5g = (const float*)d_in[8];
    const float* gn5b = (const float*)d_in[9];
    const float* wm1  = (const float*)d_in[10];
    const float* bm1  = (const float*)d_in[11];
    const float* gn6g = (const float*)d_in[12];
    const float* gn6b = (const float*)d_in[13];
    const float* wm2  = (const float*)d_in[14];
    const float* bm2  = (const float*)d_in[15];
    const float* gn7g = (const float*)d_in[16];
    const float* gn7b = (const float*)d_in[17];
    const float* wm3  = (const float*)d_in[18];
    const float* bm3  = (const float*)d_in[19];
    const float* gn8g = (const float*)d_in[20];
    const float* gn8b = (const float*)d_in[21];
    float* out = (float*)d_out;

    #define SYM(v, s) float* v; cudaGetSymbolAddress((void**)&v, s)
    #define SYU(v, s) unsigned* v; cudaGetSymbolAddress((void**)&v, s)
    SYM(simi, g_simi); SYM(y3t, g_y3t); SYM(gsA, g_gsA);
    SYM(h5, g_h5); SYM(h6, g_h6); SYM(h7, g_h7); SYM(embp, g_embp);
    SYU(xnh, g_xn_h); SYU(xnl, g_xn_l); SYU(ynh, g_yn_h); SYU(ynl, g_yn_l);
    SYU(xch, g_xc_h); SYU(xcl, g_xc_l); SYU(xfh, g_xf_h); SYU(xfl, g_xf_l);
    SYU(h5h, g_h5_h); SYU(h5l, g_h5_l); SYU(h6h, g_h6_h); SYU(h6l, g_h6_l);
    SYU(h7h, g_h7_h); SYU(h7l, g_h7_l);
    SYU(w4h, g_w4_h); SYU(w4l, g_w4_l); SYU(w5h, g_w5_h); SYU(w5l, g_w5_l);
    SYU(m1h, g_m1_h); SYU(m1l, g_m1_l); SYU(m2h, g_m2_h); SYU(m2l, g_m2_l);
    SYU(m3h, g_m3_h); SYU(m3l, g_m3_l);
    float* gs0 = gsA;        float* gs1 = gsA + 512;
    float* gs2 = gsA + 1024; float* gs3 = gsA + 1536;

    const int GSM = 81920;
    cudaFuncSetAttribute(gemm_hl<0>, cudaFuncAttributeMaxDynamicSharedMemorySize, GSM);
    cudaFuncSetAttribute(gemm_hl<1>, cudaFuncAttributeMaxDynamicSharedMemorySize, GSM);
    cudaFuncSetAttribute(gemm_hl<3>, cudaFuncAttributeMaxDynamicSharedMemorySize, GSM);

    dim3 tb(32, 8);

    // prologue; ncu capture lands on launch #4 = simi GEMM
    transpose_hl<<<dim3(64,4,8), tb>>>(x3, xfh, xfl, 128, 256, 64);   // 1
    transpose_f <<<dim3(64,4,8), tb>>>(y3, y3t, 128);                 // 2
    norm_xy<<<dim3(PT/4, 2), dim3(64,4)>>>(xnh, xnl, ynh, ynl);       // 3

    // cosine similarity, full batch (fp32 simi — fp16 failed precision in R15)
    gemm_hl<0><<<dim3(16,16,8), 256, GSM>>>(xnh, xnl, ynh, ynl, simi, // 4 <- profiled
                                            nullptr, nullptr, 128, 2048, 0,
                                            (size_t)NPT*64, (size_t)NPT*64,
                                            (size_t)NPT*NPT, nullptr, nullptr,
                                            nullptr, 0);
    transpose_hl<<<dim3(64,2,8), tb>>>(x1, xfh, xfl, 64, 256, 0);
    transpose_hl<<<dim3(64,2,8), tb>>>(x2, xfh, xfl, 64, 256, 32);
    zero_init_kernel<<<16, 256>>>();
    wsplit_all<<<1472, 256>>>(w4, w5, wm1, wm2, wm3);

    topk_agg<<<PT, 256>>>();

    // conv4: BN+lrelu, hi/lo out into xfull cols [256..512)
    gemm_hl<1><<<dim3(2,128,1), 256, GSM>>>(xch, xcl, w4h, w4l, nullptr, xfh, xfl,
                                            256, 512, 128, 0,0,0, bn4g, bn4b,
                                            nullptr, 0);

    // conv5: raw fp32 + group stats in epilogue (buffer 0)
    gemm_hl<3><<<dim3(4,128,1), 256, GSM>>>(xfh, xfl, w5h, w5l, h5, nullptr, nullptr,
                                            512, 512, 0, 0,0,0, nullptr, nullptr,
                                            gs0, 4);
    gn_apply5_hl<<<dim3(16,8), 256>>>(h5, h5h, h5l, gn5g, gn5b, gs0);

    // mlp conv1 (buffer 1)
    gemm_hl<3><<<dim3(4,128,1), 256, GSM>>>(h5h, h5l, m1h, m1l, h6, nullptr, nullptr,
                                            512, 512, 0, 0,0,0, nullptr, bm1,
                                            gs1, 4);
    gn_apply_hl<<<8192, 256>>>(h6, h6h, h6l, gn6g, gn6b, gs1, 1.f/32768.f, 9, 4);

    // mlp conv2 (buffer 2)
    gemm_hl<3><<<dim3(2,128,1), 256, GSM>>>(h6h, h6l, m2h, m2l, h7, nullptr, nullptr,
                                            512, 256, 0, 0,0,0, nullptr, bm2,
                                            gs2, 3);
    gn_apply_hl<<<4096, 256>>>(h7, h7h, h7l, gn7g, gn7b, gs2, 1.f/16384.f, 8, 3);

    // mlp conv3 (buffer 3)
    gemm_hl<3><<<dim3(1,128,1), 256, GSM>>>(h7h, h7l, m3h, m3l, embp, nullptr, nullptr,
                                            256, 128, 0, 0,0,0, nullptr, bm3,
                                            gs3, 2);

    // fused final GN + ReLU + output transpose (inline stats, buffer 3)
    gn_emb_out<<<dim3(64,4,8), tb>>>(embp, out, gn8g, gn8b, gs3);
    gv_out <<<8, 1024>>>(out + (size_t)BB*128*NPT);
}

// round 17
// speedup vs baseline: 1.0254x; 1.0254x over previous
#include <cuda_runtime.h>
#include <cuda_bf16.h>
#include <math.h>

#define BB 8
#define NPT 2048
#define PT (BB*NPT)

// ---------------- scratch (device globals; no runtime allocation) ----------------
__device__ float g_simi[(size_t)BB*NPT*NPT];
__device__ float g_y3t [(size_t)PT*128];
__device__ unsigned g_xn_h[(size_t)PT*64],  g_xn_l[(size_t)PT*64];
__device__ unsigned g_yn_h[(size_t)PT*64],  g_yn_l[(size_t)PT*64];
__device__ unsigned g_xc_h[(size_t)PT*128], g_xc_l[(size_t)PT*128];
__device__ unsigned g_xf_h[(size_t)PT*256], g_xf_l[(size_t)PT*256];
__device__ float    g_h5 [(size_t)PT*512];
__device__ unsigned g_h5_h[(size_t)PT*256], g_h5_l[(size_t)PT*256];
__device__ float    g_h6 [(size_t)PT*512];
__device__ unsigned g_h6_h[(size_t)PT*256], g_h6_l[(size_t)PT*256];
__device__ float    g_h7 [(size_t)PT*256];
__device__ unsigned g_h7_h[(size_t)PT*128], g_h7_l[(size_t)PT*128];
__device__ float    g_embp[(size_t)PT*128];
__device__ unsigned g_w4_h[256*128],  g_w4_l[256*128];
__device__ unsigned g_w5_h[512*256],  g_w5_l[512*256];
__device__ unsigned g_m1_h[512*256],  g_m1_l[512*256];
__device__ unsigned g_m2_h[256*256],  g_m2_l[256*256];
__device__ unsigned g_m3_h[128*128],  g_m3_l[128*128];
__device__ float g_gsA[4*512];           // per-layer GN accumulators (sum, sumsq)
__device__ float g_gsum[BB*512];
__device__ unsigned g_gmax[BB*512];

// ---------------- helpers ----------------------------------------------------------
__device__ __forceinline__ void split2(float a, float b, unsigned& hi, unsigned& lo) {
    __nv_bfloat162 h = __floats2bfloat162_rn(a, b);
    float ra = a - __bfloat162float(h.x);
    float rb = b - __bfloat162float(h.y);
    __nv_bfloat162 l = __floats2bfloat162_rn(ra, rb);
    hi = *reinterpret_cast<unsigned*>(&h);
    lo = *reinterpret_cast<unsigned*>(&l);
}
__device__ __forceinline__ float hl_lo(unsigned h, unsigned l) {
    return __uint_as_float(h << 16) + __uint_as_float(l << 16);
}
__device__ __forceinline__ float hl_hi(unsigned h, unsigned l) {
    return __uint_as_float(h & 0xffff0000u) + __uint_as_float(l & 0xffff0000u);
}

#define MMA_BF16(ACC, AF, BF) \
    asm volatile( \
        "mma.sync.aligned.m16n8k16.row.col.f32.bf16.bf16.f32 " \
        "{%0,%1,%2,%3}, {%4,%5,%6,%7}, {%8,%9}, {%0,%1,%2,%3};" \
        : "+f"(ACC[0]), "+f"(ACC[1]), "+f"(ACC[2]), "+f"(ACC[3]) \
        : "r"(AF[0]), "r"(AF[1]), "r"(AF[2]), "r"(AF[3]), \
          "r"(BF[0]), "r"(BF[1]))

#define CPA16(DSTU, SRC) \
    asm volatile("cp.async.cg.shared.global [%0], [%1], 16;" :: "r"(DSTU), "l"(SRC))

#define LDSM_X4(R, ADR) \
    asm volatile("ldmatrix.sync.aligned.m8n8.x4.shared.b16 {%0,%1,%2,%3}, [%4];" \
        : "=r"((R)[0]), "=r"((R)[1]), "=r"((R)[2]), "=r"((R)[3]) : "r"(ADR))

// ---------------- init --------------------------------------------------------------
__global__ void zero_init_kernel() {
    int i = blockIdx.x*blockDim.x + threadIdx.x;
    if (i < BB*512) { g_gsum[i] = 0.f; g_gmax[i] = 0u; }
    if (i < 4*512)  g_gsA[i] = 0.f;
}

// ---------------- all weight splits, one launch -------------------------------------
__global__ void wsplit_all(const float* __restrict__ w4, const float* __restrict__ w5,
                           const float* __restrict__ m1, const float* __restrict__ m2,
                           const float* __restrict__ m3) {
    int t = blockIdx.x*256 + threadIdx.x;
    const float* src; unsigned *dh, *dl; int li;
    if      (t < 32768)  { src = w4; dh = g_w4_h; dl = g_w4_l; li = t; }
    else if (t < 163840) { src = w5; dh = g_w5_h; dl = g_w5_l; li = t - 32768; }
    else if (t < 294912) { src = m1; dh = g_m1_h; dl = g_m1_l; li = t - 163840; }
    else if (t < 360448) { src = m2; dh = g_m2_h; dl = g_m2_l; li = t - 294912; }
    else if (t < 376832) { src = m3; dh = g_m3_h; dl = g_m3_l; li = t - 360448; }
    else return;
    float2 v = ((const float2*)src)[li];
    unsigned h, l; split2(v.x, v.y, h, l);
    dh[li] = h; dl[li] = l;
}

// ---------------- [B,C,N] -> point-major hi/lo ---------------------------------------
__global__ void transpose_hl(const float* __restrict__ src, unsigned* __restrict__ dh,
                             unsigned* __restrict__ dl, int C, int dstLdU, int dstOffU) {
    __shared__ float tile[32][33];
    int b  = blockIdx.z;
    int n0 = blockIdx.x*32, c0 = blockIdx.y*32;
    const float* s = src + (size_t)b*C*NPT;
    for (int i = threadIdx.y; i < 32; i += 8)
        tile[i][threadIdx.x] = s[(size_t)(c0+i)*NPT + n0 + threadIdx.x];
    __syncthreads();
    int tid = threadIdx.y*32 + threadIdx.x;
    #pragma unroll
    for (int it = 0; it < 2; it++) {
        int pl = (tid >> 4) + it*16, up = tid & 15;
        unsigned h, l;
        split2(tile[up*2][pl], tile[up*2+1][pl], h, l);
        size_t idx = (size_t)(b*NPT + n0 + pl)*dstLdU + dstOffU + (c0 >> 1) + up;
        dh[idx] = h; dl[idx] = l;
    }
}

// ---------------- x1 & x2 (64ch) -> xfull hi/lo, one launch -------------------------
__global__ void transpose_hl2(const float* __restrict__ x1, const float* __restrict__ x2) {
    __shared__ float tile[32][33];
    int z  = blockIdx.z;
    int b  = z & 7, sel = z >> 3;
    const float* src = sel ? x2 : x1;
    int dstOffU = sel ? 32 : 0;
    int n0 = blockIdx.x*32, c0 = blockIdx.y*32;
    const float* s = src + (size_t)b*64*NPT;
    for (int i = threadIdx.y; i < 32; i += 8)
        tile[i][threadIdx.x] = s[(size_t)(c0+i)*NPT + n0 + threadIdx.x];
    __syncthreads();
    int tid = threadIdx.y*32 + threadIdx.x;
    #pragma unroll
    for (int it = 0; it < 2; it++) {
        int pl = (tid >> 4) + it*16, up = tid & 15;
        unsigned h, l;
        split2(tile[up*2][pl], tile[up*2+1][pl], h, l);
        size_t idx = (size_t)(b*NPT + n0 + pl)*256 + dstOffU + (c0 >> 1) + up;
        g_xf_h[idx] = h; g_xf_l[idx] = l;
    }
}

// ---------------- [B,C,N] -> point-major fp32 ---------------------------------------
__global__ void transpose_f(const float* __restrict__ src, float* __restrict__ dst, int C) {
    __shared__ float tile[32][33];
    int b  = blockIdx.z;
    int n0 = blockIdx.x*32, c0 = blockIdx.y*32;
    const float* s = src + (size_t)b*C*NPT;
    for (int i = threadIdx.y; i < 32; i += 8)
        tile[i][threadIdx.x] = s[(size_t)(c0+i)*NPT + n0 + threadIdx.x];
    __syncthreads();
    float* d = dst + (size_t)b*NPT*C;
    for (int i = threadIdx.y; i < 32; i += 8)
        d[(size_t)(n0+i)*C + c0 + threadIdx.x] = tile[threadIdx.x][i];
}

// ---------------- L2 normalize: x (hi/lo source) and y (fp32 source) merged ---------
__global__ void norm_xy(unsigned* __restrict__ xnh, unsigned* __restrict__ xnl,
                        unsigned* __restrict__ ynh, unsigned* __restrict__ ynl) {
    int p = blockIdx.x*4 + threadIdx.y;
    int t = threadIdx.x;
    float v0, v1;
    if (blockIdx.y == 0) {
        unsigned h = g_xf_h[(size_t)p*256 + 64 + t], l = g_xf_l[(size_t)p*256 + 64 + t];
        v0 = hl_lo(h, l); v1 = hl_hi(h, l);
    } else {
        float2 v = ((const float2*)g_y3t)[(size_t)p*64 + t];
        v0 = v.x; v1 = v.y;
    }
    float s = v0*v0 + v1*v1;
    #pragma unroll
    for (int o = 16; o; o >>= 1) s += __shfl_xor_sync(0xffffffffu, s, o);
    __shared__ float ws[8];
    int wid = threadIdx.y*2 + (t >> 5);
    if ((t & 31) == 0) ws[wid] = s;
    __syncthreads();
    float rs = rsqrtf(ws[threadIdx.y*2] + ws[threadIdx.y*2+1]);
    unsigned oh, ol; split2(v0*rs, v1*rs, oh, ol);
    if (blockIdx.y == 0) { xnh[(size_t)p*64 + t] = oh; xnl[(size_t)p*64 + t] = ol; }
    else                 { ynh[(size_t)p*64 + t] = oh; ynl[(size_t)p*64 + t] = ol; }
}

// ---------------- bf16x3 GEMM, cp.async pipeline + ldmatrix fragments --------------
// EPI 0: fp32 out   EPI 1: BN+LeakyReLU -> hi/lo   EPI 3: (+bias) fp32 + group stats
template<int EPI>
__global__ void __launch_bounds__(256, 2) gemm_hl(
    const unsigned* __restrict__ Ah, const unsigned* __restrict__ Al,
    const unsigned* __restrict__ Bh, const unsigned* __restrict__ Bl,
    float* __restrict__ C, unsigned* __restrict__ Ch, unsigned* __restrict__ Cl,
    int K, int ldc, int coffU,
    size_t sAU, size_t sBU, size_t sC,
    const float* __restrict__ p1, const float* __restrict__ p2,
    float* __restrict__ gsb, int chgShift)
{
    extern __shared__ __align__(16) unsigned sm[];
    __shared__ float sgs[64];
    const int KU = K >> 1;
    Ah += sAU*blockIdx.z; Al += sAU*blockIdx.z;
    Bh += sBU*blockIdx.z; Bl += sBU*blockIdx.z;
    C  += sC*blockIdx.z;
    const int row0 = blockIdx.y*128, col0 = blockIdx.x*128;
    const int tid  = threadIdx.x;
    const int lane = tid & 31, warp = tid >> 5;
    const int warpM = warp & 1, warpN = warp >> 1;

    if (EPI == 3 && tid < 64) sgs[tid] = 0.f;

    unsigned sbase = (unsigned)__cvta_generic_to_shared(sm);
    const int r0 = tid >> 2, q0 = (tid & 3) << 2;
    const unsigned aoff = (unsigned)((lane & 15)*80 + (lane >> 4)*16);
    const unsigned boff = (unsigned)(((lane & 7) + ((lane >> 4) << 3))*80
                                     + ((lane >> 3) & 1)*16);

    float acc[4][4][4];
    #pragma unroll
    for (int mi = 0; mi < 4; mi++)
        #pragma unroll
        for (int ni = 0; ni < 4; ni++)
            #pragma unroll
            for (int q = 0; q < 4; q++) acc[mi][ni][q] = 0.f;

    const int nk = K >> 5;

    auto issue = [&](int t, int stage) {
        int ku0 = (t << 4) + q0;
        unsigned dbase = sbase + (stage*10240 + r0*20 + q0)*4u;
        #pragma unroll
        for (int i = 0; i < 2; i++) {
            int r = r0 + i*64;
            unsigned d = dbase + i*(64*20*4u);
            CPA16(d,            Ah + (size_t)(row0+r)*KU + ku0);
            CPA16(d + 2560*4u,  Al + (size_t)(row0+r)*KU + ku0);
            CPA16(d + 5120*4u,  Bh + (size_t)(col0+r)*KU + ku0);
            CPA16(d + 7680*4u,  Bl + (size_t)(col0+r)*KU + ku0);
        }
        asm volatile("cp.async.commit_group;");
    };

    issue(0, 0);

    for (int t = 0; t < nk; t++) {
        int stage = t & 1;
        if (t + 1 < nk) {
            issue(t + 1, stage ^ 1);
            asm volatile("cp.async.wait_group 1;");
        } else {
            asm volatile("cp.async.wait_group 0;");
        }
        __syncthreads();
        unsigned stg = sbase + (unsigned)stage*40960u;
        #pragma unroll
        for (int kk = 0; kk < 2; kk++) {
            unsigned ah[4][4], al[4][4], bh[4][2], bl[4][2];
            #pragma unroll
            for (int mi = 0; mi < 4; mi++) {
                unsigned adr = stg + (unsigned)(((warpM*64 + mi*16)*20 + kk*8)*4) + aoff;
                LDSM_X4(ah[mi], adr);
                LDSM_X4(al[mi], adr + 10240u);
            }
            #pragma unroll
            for (int ni2 = 0; ni2 < 2; ni2++) {
                unsigned adr = stg + 20480u
                             + (unsigned)(((warpN*32 + ni2*16)*20 + kk*8)*4) + boff;
                unsigned rb[4];
                LDSM_X4(rb, adr);
                bh[ni2*2][0] = rb[0]; bh[ni2*2][1] = rb[1];
                bh[ni2*2+1][0] = rb[2]; bh[ni2*2+1][1] = rb[3];
                LDSM_X4(rb, adr + 10240u);
                bl[ni2*2][0] = rb[0]; bl[ni2*2][1] = rb[1];
                bl[ni2*2+1][0] = rb[2]; bl[ni2*2+1][1] = rb[3];
            }
            #pragma unroll
            for (int mi = 0; mi < 4; mi++)
                #pragma unroll
                for (int ni = 0; ni < 4; ni++) {
                    MMA_BF16(acc[mi][ni], ah[mi], bh[ni]);
                    MMA_BF16(acc[mi][ni], ah[mi], bl[ni]);
                    MMA_BF16(acc[mi][ni], al[mi], bh[ni]);
                }
        }
        __syncthreads();
    }

    float ls1[4] = {0.f,0.f,0.f,0.f}, ls2[4] = {0.f,0.f,0.f,0.f};

    #pragma unroll
    for (int mi = 0; mi < 4; mi++) {
        int r = row0 + warpM*64 + mi*16 + (lane >> 2);
        #pragma unroll
        for (int ni = 0; ni < 4; ni++) {
            int cc = col0 + warpN*32 + ni*8 + (lane & 3)*2;
            #pragma unroll
            for (int half = 0; half < 2; half++) {
                int rr = r + half*8;
                float v0 = acc[mi][ni][half*2 + 0];
                float v1 = acc[mi][ni][half*2 + 1];
                if (EPI == 1) {
                    v0 = v0 * (p1[cc]   * 0.9999950000374998f) + p2[cc];
                    v1 = v1 * (p1[cc+1] * 0.9999950000374998f) + p2[cc+1];
                    v0 = v0 >= 0.f ? v0 : 0.2f*v0;
                    v1 = v1 >= 0.f ? v1 : 0.2f*v1;
                    unsigned oh, ol; split2(v0, v1, oh, ol);
                    size_t idx = (size_t)rr*(ldc>>1) + coffU + (cc >> 1);
                    Ch[idx] = oh; Cl[idx] = ol;
                } else {
                    if (EPI == 3 && p2) { v0 += p2[cc]; v1 += p2[cc+1]; }
                    *(float2*)(C + (size_t)rr*ldc + cc) = make_float2(v0, v1);
                    if (EPI == 3) {
                        ls1[ni] += v0 + v1;
                        ls2[ni] += v0*v0 + v1*v1;
                    }
                }
            }
        }
    }

    if (EPI == 3) {
        int b = row0 >> 11;
        if (chgShift >= 3) {
            #pragma unroll
            for (int ni = 0; ni < 4; ni++) {
                float v1s = ls1[ni], v2s = ls2[ni];
                #pragma unroll
                for (int o = 16; o; o >>= 1) {
                    v1s += __shfl_xor_sync(0xffffffffu, v1s, o);
                    v2s += __shfl_xor_sync(0xffffffffu, v2s, o);
                }
                if (lane == 0) {
                    int gl = (warpN*32 + ni*8) >> chgShift;
                    atomicAdd(&sgs[gl*2],   v1s);
                    atomicAdd(&sgs[gl*2+1], v2s);
                }
            }
        } else {
            #pragma unroll
            for (int ni = 0; ni < 4; ni++) {
                int gl = (warpN*32 + ni*8 + (lane & 3)*2) >> chgShift;
                atomicAdd(&sgs[gl*2],   ls1[ni]);
                atomicAdd(&sgs[gl*2+1], ls2[ni]);
            }
        }
        __syncthreads();
        int ng = 128 >> chgShift;
        if (tid < ng) {
            int g = (col0 >> chgShift) + tid;
            atomicAdd(&gsb[(b*32 + g)*2],   sgs[tid*2]);
            atomicAdd(&gsb[(b*32 + g)*2+1], sgs[tid*2+1]);
        }
    }
}

// ---------------- top-20 + softmax + neighbor aggregation (R14 smem form) -----------
__global__ void __launch_bounds__(256) topk_agg() {
    __shared__ float row[2048];
    __shared__ float tv[20]; __shared__ int tix[20];
    __shared__ float wgt[20];
    __shared__ float wmax[8]; __shared__ int wmi[8];
    int p = blockIdx.x;
    int b = p >> 11;
    const float4* s4 = (const float4*)(g_simi + (size_t)p*2048);
    int tid = threadIdx.x;
    #pragma unroll
    for (int i = 0; i < 2; i++)
        ((float4*)row)[tid + i*256] = s4[tid + i*256];
    __syncthreads();

    for (int it = 0; it < 20; it++) {
        float m = -INFINITY; int mi = 0x7fffffff;
        for (int i = tid; i < 2048; i += 256) {
            float v = row[i];
            if (v > m) { m = v; mi = i; }
        }
        #pragma unroll
        for (int o = 16; o; o >>= 1) {
            float ov = __shfl_xor_sync(0xffffffffu, m, o);
            int   oi = __shfl_xor_sync(0xffffffffu, mi, o);
            if (ov > m || (ov == m && oi < mi)) { m = ov; mi = oi; }
        }
        if ((tid & 31) == 0) { wmax[tid>>5] = m; wmi[tid>>5] = mi; }
        __syncthreads();
        if (tid == 0) {
            float bm = wmax[0]; int bi = wmi[0];
            for (int w = 1; w < 8; w++)
                if (wmax[w] > bm || (wmax[w] == bm && wmi[w] < bi)) { bm = wmax[w]; bi = wmi[w]; }
            tv[it] = bm; tix[it] = bi; row[bi] = -INFINITY;
        }
        __syncthreads();
    }

    if (tid == 0) {
        float mx = tv[0], sum = 0.f;
        float e[20];
        #pragma unroll
        for (int k = 0; k < 20; k++) { e[k] = expf(tv[k]-mx); sum += e[k]; }
        float inv = 1.f/sum;
        #pragma unroll
        for (int k = 0; k < 20; k++) wgt[k] = e[k]*inv;
    }
    __syncthreads();

    if (tid < 64) {
        g_xc_h[(size_t)p*128 + tid] = g_xf_h[(size_t)p*256 + 64 + tid];
        g_xc_l[(size_t)p*128 + tid] = g_xf_l[(size_t)p*256 + 64 + tid];
    } else if (tid < 128) {
        int t2 = tid - 64;
        const float2* yb = (const float2*)(g_y3t + (size_t)b*NPT*128);
        float a0 = 0.f, a1 = 0.f;
        #pragma unroll
        for (int k = 0; k < 20; k++) {
            float2 yv = yb[(size_t)tix[k]*64 + t2];
            a0 += wgt[k]*yv.x; a1 += wgt[k]*yv.y;
        }
        unsigned h = g_xf_h[(size_t)p*256 + 64 + t2], l = g_xf_l[(size_t)p*256 + 64 + t2];
        unsigned oh, ol;
        split2(a0 - hl_lo(h, l), a1 - hl_hi(h, l), oh, ol);
        g_xc_h[(size_t)p*128 + 64 + t2] = oh;
        g_xc_l[(size_t)p*128 + 64 + t2] = ol;
    }
}

// ---------------- GN apply + ReLU -> hi/lo (inline stats, 4 elems/thread) ----------
__global__ void gn_apply_hl(const float* __restrict__ x, unsigned* __restrict__ oh,
                            unsigned* __restrict__ ol, const float* __restrict__ gam,
                            const float* __restrict__ bet, const float* __restrict__ gs,
                            float rcnt, int Cshift, int chgShift) {
    size_t q = (size_t)blockIdx.x*256 + threadIdx.x;   // quad index
    size_t e0 = q*4;
    int c0 = (int)(e0 & ((1u<<Cshift)-1u));
    int b  = (int)(e0 >> Cshift) >> 11;
    int grp = c0 >> chgShift;       // quad never crosses a group (chgShift >= 3)
    float s1 = gs[(b*32+grp)*2], s2 = gs[(b*32+grp)*2+1];
    float mu = s1*rcnt;
    float rs = rsqrtf(s2*rcnt - mu*mu + 1e-5f);
    float4 xv = ((const float4*)x)[q];
    float v0 = fmaxf((xv.x-mu)*rs*gam[c0]   + bet[c0],   0.f);
    float v1 = fmaxf((xv.y-mu)*rs*gam[c0+1] + bet[c0+1], 0.f);
    float v2 = fmaxf((xv.z-mu)*rs*gam[c0+2] + bet[c0+2], 0.f);
    float v3 = fmaxf((xv.w-mu)*rs*gam[c0+3] + bet[c0+3], 0.f);
    unsigned h0, l0, h1, l1;
    split2(v0, v1, h0, l0);
    split2(v2, v3, h1, l1);
    oh[q*2] = h0; oh[q*2+1] = h1;
    ol[q*2] = l0; ol[q*2+1] = l1;
}

// ---------------- conv5 GN apply + LeakyReLU + gmax/gavg -> hi/lo (inline stats) ----
__global__ void gn_apply5_hl(const float* __restrict__ x, unsigned* __restrict__ oh,
                             unsigned* __restrict__ ol, const float* __restrict__ gam,
                             const float* __restrict__ bet, const float* __restrict__ gs) {
    int b = blockIdx.y;
    int p0 = blockIdx.x*128;
    int t = threadIdx.x;
    int c0 = t*2;
    int grp = c0 >> 4;
    float s1v = gs[(b*32+grp)*2], s2v = gs[(b*32+grp)*2+1];
    float mu = s1v*(1.f/32768.f);
    float rs = rsqrtf(s2v*(1.f/32768.f) - mu*mu + 1e-5f);
    float ga0 = rs*gam[c0],   bb0 = bet[c0]   - mu*ga0;
    float ga1 = rs*gam[c0+1], bb1 = bet[c0+1] - mu*ga1;
    float s0 = 0.f, s1 = 0.f, m0 = -INFINITY, m1 = -INFINITY;
    size_t base = ((size_t)b*NPT + p0)*256 + t;
    for (int p = 0; p < 128; p++) {
        size_t idx = base + (size_t)p*256;
        float2 xv = ((const float2*)x)[idx];
        float v0 = xv.x*ga0 + bb0; v0 = v0 >= 0.f ? v0 : 0.2f*v0;
        float v1 = xv.y*ga1 + bb1; v1 = v1 >= 0.f ? v1 : 0.2f*v1;
        unsigned h, l; split2(v0, v1, h, l);
        oh[idx] = h; ol[idx] = l;
        s0 += v0; s1 += v1; m0 = fmaxf(m0, v0); m1 = fmaxf(m1, v1);
    }
    atomicAdd(&g_gsum[b*512+c0],   s0);
    atomicAdd(&g_gsum[b*512+c0+1], s1);
    unsigned u0 = __float_as_uint(m0);
    u0 = (u0 & 0x80000000u) ? ~u0 : (u0 | 0x80000000u);
    atomicMax(&g_gmax[b*512+c0], u0);
    unsigned u1 = __float_as_uint(m1);
    u1 = (u1 & 0x80000000u) ? ~u1 : (u1 | 0x80000000u);
    atomicMax(&g_gmax[b*512+c0+1], u1);
}

// ---------------- FUSED: emb GN apply + ReLU + transpose (inline stats) -------------
__global__ void gn_emb_out(const float* __restrict__ e, float* __restrict__ dst,
                           const float* __restrict__ gam, const float* __restrict__ bet,
                           const float* __restrict__ gs) {
    __shared__ float tile[32][33];
    int b = blockIdx.z;
    int n0 = blockIdx.x*32, c0 = blockIdx.y*32;
    int c = c0 + threadIdx.x;
    int grp = c >> 2;
    float s1 = gs[(b*32+grp)*2], s2 = gs[(b*32+grp)*2+1];
    float mu = s1*(1.f/8192.f);
    float rs = rsqrtf(s2*(1.f/8192.f) - mu*mu + 1e-5f);
    float ga = rs*gam[c], bb = bet[c] - mu*ga;
    const float* s = e + (size_t)b*NPT*128;
    for (int i = threadIdx.y; i < 32; i += 8) {
        float v = s[(size_t)(n0+i)*128 + c];
        tile[i][threadIdx.x] = fmaxf(v*ga + bb, 0.f);
    }
    __syncthreads();
    float* d = dst + (size_t)b*128*NPT;
    for (int i = threadIdx.y; i < 32; i += 8)
        d[(size_t)(c0+i)*NPT + n0 + threadIdx.x] = tile[threadIdx.x][i];
}

// ---------------- output: global vector [B,1024] -----------------------------------
__global__ void gv_out(float* __restrict__ dst) {
    int i = blockIdx.x*blockDim.x + threadIdx.x;
    int b = i >> 10, c = i & 1023;
    float v;
    if (c < 512) {
        unsigned u = g_gmax[b*512+c];
        unsigned f = (u & 0x80000000u) ? (u ^ 0x80000000u) : ~u;
        v = __uint_as_float(f);
    } else {
        v = g_gsum[b*512 + c - 512] * (1.f/2048.f);
    }
    dst[i] = v;
}

// ===================================================================================
extern "C" void kernel_launch(void* const* d_in, const int* in_sizes, int n_in,
                              void* d_out, int out_size) {
    const float* x1   = (const float*)d_in[0];
    const float* x2   = (const float*)d_in[1];
    const float* x3   = (const float*)d_in[2];
    const float* y3   = (const float*)d_in[3];
    const float* w4   = (const float*)d_in[4];
    const float* bn4g = (const float*)d_in[5];
    const float* bn4b = (const float*)d_in[6];
    const float* w5   = (const float*)d_in[7];
    const float* gn5g = (const float*)d_in[8];
    const float* gn5b = (const float*)d_in[9];
    const float* wm1  = (const float*)d_in[10];
    const float* bm1  = (const float*)d_in[11];
    const float* gn6g = (const float*)d_in[12];
    const float* gn6b = (const float*)d_in[13];
    const float* wm2  = (const float*)d_in[14];
    const float* bm2  = (const float*)d_in[15];
    const float* gn7g = (const float*)d_in[16];
    const float* gn7b = (const float*)d_in[17];
    const float* wm3  = (const float*)d_in[18];
    const float* bm3  = (const float*)d_in[19];
    const float* gn8g = (const float*)d_in[20];
    const float* gn8b = (const float*)d_in[21];
    float* out = (float*)d_out;

    #define SYM(v, s) float* v; cudaGetSymbolAddress((void**)&v, s)
    #define SYU(v, s) unsigned* v; cudaGetSymbolAddress((void**)&v, s)
    SYM(simi, g_simi); SYM(y3t, g_y3t); SYM(gsA, g_gsA);
    SYM(h5, g_h5); SYM(h6, g_h6); SYM(h7, g_h7); SYM(embp, g_embp);
    SYU(xnh, g_xn_h); SYU(xnl, g_xn_l); SYU(ynh, g_yn_h); SYU(ynl, g_yn_l);
    SYU(xch, g_xc_h); SYU(xcl, g_xc_l); SYU(xfh, g_xf_h); SYU(xfl, g_xf_l);
    SYU(h5h, g_h5_h); SYU(h5l, g_h5_l); SYU(h6h, g_h6_h); SYU(h6l, g_h6_l);
    SYU(h7h, g_h7_h); SYU(h7l, g_h7_l);
    SYU(w4h, g_w4_h); SYU(w4l, g_w4_l); SYU(w5h, g_w5_h); SYU(w5l, g_w5_l);
    SYU(m1h, g_m1_h); SYU(m1l, g_m1_l); SYU(m2h, g_m2_h); SYU(m2l, g_m2_l);
    SYU(m3h, g_m3_h); SYU(m3l, g_m3_l);
    float* gs0 = gsA;        float* gs1 = gsA + 512;
    float* gs2 = gsA + 1024; float* gs3 = gsA + 1536;

    const int GSM = 81920;
    cudaFuncSetAttribute(gemm_hl<0>, cudaFuncAttributeMaxDynamicSharedMemorySize, GSM);
    cudaFuncSetAttribute(gemm_hl<1>, cudaFuncAttributeMaxDynamicSharedMemorySize, GSM);
    cudaFuncSetAttribute(gemm_hl<3>, cudaFuncAttributeMaxDynamicSharedMemorySize, GSM);

    dim3 tb(32, 8);

    // prologue; ncu capture lands on launch #4 = simi GEMM
    transpose_hl<<<dim3(64,4,8), tb>>>(x3, xfh, xfl, 128, 256, 64);   // 1
    transpose_f <<<dim3(64,4,8), tb>>>(y3, y3t, 128);                 // 2
    norm_xy<<<dim3(PT/4, 2), dim3(64,4)>>>(xnh, xnl, ynh, ynl);       // 3

    // cosine similarity, full batch (fp32 simi)
    gemm_hl<0><<<dim3(16,16,8), 256, GSM>>>(xnh, xnl, ynh, ynl, simi, // 4 <- profiled
                                            nullptr, nullptr, 128, 2048, 0,
                                            (size_t)NPT*64, (size_t)NPT*64,
                                            (size_t)NPT*NPT, nullptr, nullptr,
                                            nullptr, 0);
    transpose_hl2<<<dim3(64,2,16), tb>>>(x1, x2);
    zero_init_kernel<<<16, 256>>>();
    wsplit_all<<<1472, 256>>>(w4, w5, wm1, wm2, wm3);

    topk_agg<<<PT, 256>>>();

    // conv4: BN+lrelu, hi/lo out into xfull cols [256..512)
    gemm_hl<1><<<dim3(2,128,1), 256, GSM>>>(xch, xcl, w4h, w4l, nullptr, xfh, xfl,
                                            256, 512, 128, 0,0,0, bn4g, bn4b,
                                            nullptr, 0);

    // conv5: raw fp32 + group stats in epilogue (buffer 0)
    gemm_hl<3><<<dim3(4,128,1), 256, GSM>>>(xfh, xfl, w5h, w5l, h5, nullptr, nullptr,
                                            512, 512, 0, 0,0,0, nullptr, nullptr,
                                            gs0, 4);
    gn_apply5_hl<<<dim3(16,8), 256>>>(h5, h5h, h5l, gn5g, gn5b, gs0);

    // mlp conv1 (buffer 1)
    gemm_hl<3><<<dim3(4,128,1), 256, GSM>>>(h5h, h5l, m1h, m1l, h6, nullptr, nullptr,
                                            512, 512, 0, 0,0,0, nullptr, bm1,
                                            gs1, 4);
    gn_apply_hl<<<8192, 256>>>(h6, h6h, h6l, gn6g, gn6b, gs1, 1.f/32768.f, 9, 4);

    // mlp conv2 (buffer 2)
    gemm_hl<3><<<dim3(2,128,1), 256, GSM>>>(h6h, h6l, m2h, m2l, h7, nullptr, nullptr,
                                            512, 256, 0, 0,0,0, nullptr, bm2,
                                            gs2, 3);
    gn_apply_hl<<<4096, 256>>>(h7, h7h, h7l, gn7g, gn7b, gs2, 1.f/16384.f, 8, 3);

    // mlp conv3 (buffer 3)
    gemm_hl<3><<<dim3(1,128,1), 256, GSM>>>(h7h, h7l, m3h, m3l, embp, nullptr, nullptr,
                                            256, 128, 0, 0,0,0, nullptr, bm3,
                                            gs3, 2);

    // fused final GN + ReLU + output transpose (inline stats, buffer 3)
    gn_emb_out<<<dim3(64,4,8), tb>>>(embp, out, gn8g, gn8b, gs3);
    gv_out <<<8, 1024>>>(out + (size_t)BB*128*NPT);
}